// round 7
// baseline (speedup 1.0000x reference)
#include <cuda_runtime.h>
#include <cstdint>
#include <cstddef>

#define T_ 256
#define B_ 128
#define I_ 64
#define C_ 256
#define H_ 512
#define O_ 128
#define CI_ 16384      // C_*I_
#define NCTA 128
#define NTHR 256
#define KSPLIT 32
#define KPER 512       // CI_/KSPLIT

// -------------------- scratch (static device allocations are allowed) ------
__device__ float g_W2[(size_t)H_ * CI_];            // 32 MB: W2[h][c*I+i] = Wmap[(h*I+i)*C + c]
__device__ float g_ctx[2][B_ * C_];                 // ctx double buffer
__device__ float g_hpart[KSPLIT][B_ * H_];          // 8 MB partial sums of heavy GEMM
__device__ float g_h1[B_ * H_];                     // h after relu
__device__ unsigned g_cnt;
__device__ volatile unsigned g_gen;

// -------------------- grid-wide barrier (all NCTA CTAs co-resident) --------
__device__ __forceinline__ void grid_sync() {
    __syncthreads();
    if (threadIdx.x == 0) {
        __threadfence();
        unsigned gen = g_gen;
        if (atomicAdd(&g_cnt, 1u) == NCTA - 1) {
            g_cnt = 0;
            __threadfence();
            g_gen = gen + 1;
        } else {
            while (g_gen == gen) { __nanosleep(64); }
        }
        __threadfence();
    }
    __syncthreads();
}

// -------------------- setup: build W2, zero ctx0 ----------------------------
__global__ void setup_kernel(const float* __restrict__ Wmap) {
    size_t e4 = (size_t)blockIdx.x * blockDim.x + threadIdx.x;
    size_t base = e4 * 4;
    if (base < (size_t)H_ * CI_) {
#pragma unroll
        for (int j = 0; j < 4; j++) {
            size_t e = base + j;
            int h = (int)(e >> 14);          // e / CI_
            int k = (int)(e & (CI_ - 1));
            int c = k >> 6, i = k & 63;
            g_W2[e] = Wmap[((size_t)h * I_ + i) * C_ + c];
        }
    }
    if (blockIdx.x < 32) {
        int z = blockIdx.x * blockDim.x + threadIdx.x;
#pragma unroll
        for (int j = 0; j < 4; j++) g_ctx[0][z * 4 + j] = 0.f;
    }
}

// -------------------- persistent timestep kernel ----------------------------
__global__ void __launch_bounds__(NTHR)
ctrnn_persistent(const float* __restrict__ input,
                 const float* __restrict__ Wcc, const float* __restrict__ bcc,
                 const float* __restrict__ Wic, const float* __restrict__ bic,
                 const float* __restrict__ bmap,
                 const float* __restrict__ Whh, const float* __restrict__ bhh,
                 const float* __restrict__ ln_g, const float* __restrict__ ln_b,
                 const float* __restrict__ Who, const float* __restrict__ bho,
                 float* __restrict__ out, int write_ctx)
{
    __shared__ float As[8][128];      // z tile   [k][m]
    __shared__ float Bs[8][132];      // W2 tile  [k][n] (padded)
    __shared__ float Cs[128][8];      // ctx slice for this CTA's K range
    __shared__ float s_h1[H_];
    __shared__ float s_hn[H_];
    __shared__ float s_red[32];

    const int tid = threadIdx.x;

    for (int t = 0; t < T_; t++) {
        const float* xt   = input + (size_t)t * (B_ * I_);
        const float* ctxp = g_ctx[t & 1];
        float*       ctxn = g_ctx[(t + 1) & 1];

        // ================= S1: heavy GEMM partials ==========================
        {
            const int nt = blockIdx.x & 3;
            const int ks = blockIdx.x >> 2;
            const int n0 = nt * 128;
            const int k0 = ks * KPER;
            const int c0 = k0 >> 6;              // 8 ctx columns per CTA

            const int m    = tid & 127;
            const int half = tid >> 7;           // 0/1
            // stage ctx slice [128m x 8c] into smem
            {
                float4 v = *(const float4*)&ctxp[m * C_ + c0 + half * 4];
                Cs[m][half * 4 + 0] = v.x; Cs[m][half * 4 + 1] = v.y;
                Cs[m][half * 4 + 2] = v.z; Cs[m][half * 4 + 3] = v.w;
            }
            float acc[8][8];
#pragma unroll
            for (int a = 0; a < 8; a++)
#pragma unroll
                for (int b = 0; b < 8; b++) acc[a][b] = 0.f;

            const int ty = tid >> 4, tx = tid & 15;
            const int nb = tid >> 1, kq = (tid & 1) * 4;
            __syncthreads();

            for (int kb = 0; kb < KPER; kb += 8) {
                const int kg = k0 + kb;
                const int cc = (kg >> 6) - c0;   // 0..7
                const int i0 = kg & 63;
                // A tile: z[m][kk] = ctx[m][c] * x[m][i0+kk]
                {
                    float cv = Cs[m][cc];
                    float4 xv = *(const float4*)&xt[m * I_ + i0 + half * 4];
                    As[half * 4 + 0][m] = cv * xv.x;
                    As[half * 4 + 1][m] = cv * xv.y;
                    As[half * 4 + 2][m] = cv * xv.z;
                    As[half * 4 + 3][m] = cv * xv.w;
                }
                // B tile: W2[n0+nb][kg + kq .. +3]
                {
                    float4 wv = *(const float4*)&g_W2[(size_t)(n0 + nb) * CI_ + kg + kq];
                    Bs[kq + 0][nb] = wv.x; Bs[kq + 1][nb] = wv.y;
                    Bs[kq + 2][nb] = wv.z; Bs[kq + 3][nb] = wv.w;
                }
                __syncthreads();
#pragma unroll
                for (int kk = 0; kk < 8; kk++) {
                    float a[8], b[8];
                    float4 a0 = *(const float4*)&As[kk][ty * 8];
                    float4 a1 = *(const float4*)&As[kk][ty * 8 + 4];
                    a[0]=a0.x; a[1]=a0.y; a[2]=a0.z; a[3]=a0.w;
                    a[4]=a1.x; a[5]=a1.y; a[6]=a1.z; a[7]=a1.w;
                    float4 b0 = *(const float4*)&Bs[kk][tx * 8];
                    float4 b1 = *(const float4*)&Bs[kk][tx * 8 + 4];
                    b[0]=b0.x; b[1]=b0.y; b[2]=b0.z; b[3]=b0.w;
                    b[4]=b1.x; b[5]=b1.y; b[6]=b1.z; b[7]=b1.w;
#pragma unroll
                    for (int im = 0; im < 8; im++)
#pragma unroll
                        for (int in = 0; in < 8; in++)
                            acc[im][in] += a[im] * b[in];
                }
                __syncthreads();
            }
            // store partial tile
            float* hp = g_hpart[ks];
#pragma unroll
            for (int im = 0; im < 8; im++) {
                int mm = ty * 8 + im;
                float4 v0 = make_float4(acc[im][0], acc[im][1], acc[im][2], acc[im][3]);
                float4 v1 = make_float4(acc[im][4], acc[im][5], acc[im][6], acc[im][7]);
                *(float4*)&hp[(size_t)mm * H_ + n0 + tx * 8]     = v0;
                *(float4*)&hp[(size_t)mm * H_ + n0 + tx * 8 + 4] = v1;
            }
        }
        grid_sync();

        // ================= S2: reduce + relu -> h1 ; ctx update ============
        {
            const int idx = blockIdx.x * NTHR + tid;   // 0..32767
            // h1: two elements per thread
#pragma unroll
            for (int p = 0; p < 2; p++) {
                const int e = idx + p * 32768;
                const int b = e >> 9, h = e & 511;
                float s = 0.f;
#pragma unroll
                for (int ks = 0; ks < KSPLIT; ks++) s += g_hpart[ks][e];
                const float* xr = xt + b * I_;
                const float* br = bmap + (size_t)h * I_;
#pragma unroll
                for (int i = 0; i < I_; i += 4) {
                    float4 xv = *(const float4*)&xr[i];
                    float4 bv = *(const float4*)&br[i];
                    s += xv.x * bv.x + xv.y * bv.y + xv.z * bv.z + xv.w * bv.w;
                }
                g_h1[e] = fmaxf(s, 0.f);
            }
            // ctx update (exact fp32; one element per thread)
            {
                const int b = idx >> 8, cc = idx & 255;
                float s = bcc[cc] + bic[cc];
                const float* cr = ctxp + b * C_;
                const float* wr = Wcc + (size_t)cc * C_;
#pragma unroll 8
                for (int c2 = 0; c2 < C_; c2 += 4) {
                    float4 cv = *(const float4*)&cr[c2];
                    float4 wv = *(const float4*)&wr[c2];
                    s += cv.x * wv.x + cv.y * wv.y + cv.z * wv.z + cv.w * wv.w;
                }
                const float* xr = xt + b * I_;
                const float* wi = Wic + (size_t)cc * I_;
#pragma unroll
                for (int i = 0; i < I_; i += 4) {
                    float4 xv = *(const float4*)&xr[i];
                    float4 wv = *(const float4*)&wi[i];
                    s += xv.x * wv.x + xv.y * wv.y + xv.z * wv.z + xv.w * wv.w;
                }
                ctxn[idx] = fmaxf(s, 0.f);
            }
        }
        grid_sync();

        // ================= S3: Whh + LayerNorm + residual + Who ============
        if (blockIdx.x < 32) {
            const int j2 = tid >> 1, hf = tid & 1;
            for (int r = 0; r < 4; r++) {
                const int b = blockIdx.x * 4 + r;
                s_h1[tid]       = g_h1[(size_t)b * H_ + tid];
                s_h1[tid + 256] = g_h1[(size_t)b * H_ + tid + 256];
                __syncthreads();
                // hn = h1 @ Whh^T + bhh   (2 threads per row)
#pragma unroll 1
                for (int p = 0; p < 4; p++) {
                    const int j = p * 128 + j2;
                    const float* w  = Whh + (size_t)j * H_ + hf * 256;
                    const float* hv = s_h1 + hf * 256;
                    float s = 0.f;
#pragma unroll 16
                    for (int h = 0; h < 256; h += 4) {
                        float4 wv = *(const float4*)&w[h];
                        s += hv[h] * wv.x + hv[h+1] * wv.y + hv[h+2] * wv.z + hv[h+3] * wv.w;
                    }
                    s += __shfl_xor_sync(0xffffffffu, s, 1);
                    if (hf == 0) s_hn[j] = s + bhh[j];
                }
                __syncthreads();
                // layernorm stats
                float v0 = s_hn[tid], v1 = s_hn[tid + 256];
                float ss = v0 + v1, sq = v0 * v0 + v1 * v1;
#pragma unroll
                for (int o = 16; o; o >>= 1) {
                    ss += __shfl_xor_sync(0xffffffffu, ss, o);
                    sq += __shfl_xor_sync(0xffffffffu, sq, o);
                }
                if ((tid & 31) == 0) { s_red[tid >> 5] = ss; s_red[8 + (tid >> 5)] = sq; }
                __syncthreads();
                if (tid == 0) {
                    float S = 0.f, Q = 0.f;
#pragma unroll
                    for (int w = 0; w < 8; w++) { S += s_red[w]; Q += s_red[8 + w]; }
                    float mu  = S / (float)H_;
                    float var = Q / (float)H_ - mu * mu;
                    s_red[16] = mu;
                    s_red[17] = rsqrtf(var + 1e-5f);
                }
                __syncthreads();
                const float mu = s_red[16], rs = s_red[17];
#pragma unroll
                for (int jj = 0; jj < 2; jj++) {
                    const int j = tid + jj * 256;
                    float ln = (s_hn[j] - mu) * rs * ln_g[j] + ln_b[j];
                    s_hn[j] = s_h1[j] + fmaxf(ln, 0.f);
                }
                __syncthreads();
                // out = h2 @ Who^T + bho  (2 threads per output)
                {
                    const int o = tid >> 1;
                    const float* w  = Who + (size_t)o * H_ + hf * 256;
                    const float* hv = s_hn + hf * 256;
                    float s = 0.f;
#pragma unroll 16
                    for (int h = 0; h < 256; h += 4) {
                        float4 wv = *(const float4*)&w[h];
                        s += hv[h] * wv.x + hv[h+1] * wv.y + hv[h+2] * wv.z + hv[h+3] * wv.w;
                    }
                    s += __shfl_xor_sync(0xffffffffu, s, 1);
                    if (hf == 0) out[(size_t)t * (B_ * O_) + b * O_ + o] = s + bho[o];
                }
                __syncthreads();
            }
        } else if (blockIdx.x < 64) {
            // final ctx write-out (second output of the reference tuple)
            if (t == T_ - 1 && write_ctx) {
                const int idx = (blockIdx.x - 32) * NTHR + tid;   // 0..8191
                float4 v = *(const float4*)&g_ctx[0][idx * 4];    // (T)&1 == 0
                *(float4*)&out[(size_t)T_ * (B_ * O_) + (size_t)idx * 4] = v;
            }
        }
        grid_sync();
    }
}

// -------------------- launch ------------------------------------------------
extern "C" void kernel_launch(void* const* d_in, const int* in_sizes, int n_in,
                              void* d_out, int out_size) {
    const float* input = (const float*)d_in[0];
    const float* Wcc   = (const float*)d_in[1];
    const float* bcc   = (const float*)d_in[2];
    const float* Wic   = (const float*)d_in[3];
    const float* bic   = (const float*)d_in[4];
    const float* Wmap  = (const float*)d_in[5];
    const float* bmap  = (const float*)d_in[6];
    const float* Whh   = (const float*)d_in[7];
    const float* bhh   = (const float*)d_in[8];
    const float* ln_g  = (const float*)d_in[9];
    const float* ln_b  = (const float*)d_in[10];
    const float* Who   = (const float*)d_in[11];
    const float* bho   = (const float*)d_in[12];
    float* out = (float*)d_out;

    setup_kernel<<<8192, 256>>>(Wmap);

    int write_ctx = (out_size >= T_ * B_ * O_ + B_ * C_) ? 1 : 0;
    ctrnn_persistent<<<NCTA, NTHR>>>(input, Wcc, bcc, Wic, bic, bmap,
                                     Whh, bhh, ln_g, ln_b, Who, bho,
                                     out, write_ctx);
}

// round 12
// speedup vs baseline: 1.0010x; 1.0010x over previous
#include <cuda_runtime.h>
#include <cstdint>
#include <cstddef>

#define T_ 256
#define B_ 128
#define I_ 64
#define C_ 256
#define H_ 512
#define O_ 128
#define CI_ 16384      // C_*I_
#define NCTA 128
#define NTHR 256
#define KSPLIT 32
#define KPER 512       // CI_/KSPLIT

// -------------------- scratch (static device allocations are allowed) ------
__device__ float g_W2[(size_t)H_ * CI_];            // 32 MB: W2[h][c*I+i] = Wmap[(h*I+i)*C + c]
__device__ float g_ctx[2][B_ * C_];                 // ctx double buffer
__device__ float g_hpart[KSPLIT][B_ * H_];          // 8 MB partial sums of heavy GEMM
__device__ float g_h1[B_ * H_];                     // h after relu
__device__ unsigned g_cnt;
__device__ volatile unsigned g_gen;

// -------------------- grid-wide barrier (all NCTA CTAs co-resident) --------
__device__ __forceinline__ void grid_sync() {
    __syncthreads();
    if (threadIdx.x == 0) {
        __threadfence();
        unsigned gen = g_gen;
        if (atomicAdd(&g_cnt, 1u) == NCTA - 1) {
            g_cnt = 0;
            __threadfence();
            g_gen = gen + 1;
        } else {
            while (g_gen == gen) { __nanosleep(64); }
        }
        __threadfence();
    }
    __syncthreads();
}

// -------------------- setup: build W2, zero ctx0 ----------------------------
__global__ void setup_kernel(const float* __restrict__ Wmap) {
    size_t e4 = (size_t)blockIdx.x * blockDim.x + threadIdx.x;
    size_t base = e4 * 4;
    if (base < (size_t)H_ * CI_) {
#pragma unroll
        for (int j = 0; j < 4; j++) {
            size_t e = base + j;
            int h = (int)(e >> 14);          // e / CI_
            int k = (int)(e & (CI_ - 1));
            int c = k >> 6, i = k & 63;
            g_W2[e] = Wmap[((size_t)h * I_ + i) * C_ + c];
        }
    }
    if (blockIdx.x < 32) {
        int z = blockIdx.x * blockDim.x + threadIdx.x;
#pragma unroll
        for (int j = 0; j < 4; j++) g_ctx[0][z * 4 + j] = 0.f;
    }
}

// -------------------- persistent timestep kernel ----------------------------
__global__ void __launch_bounds__(NTHR)
ctrnn_persistent(const float* __restrict__ input,
                 const float* __restrict__ Wcc, const float* __restrict__ bcc,
                 const float* __restrict__ Wic, const float* __restrict__ bic,
                 const float* __restrict__ bmap,
                 const float* __restrict__ Whh, const float* __restrict__ bhh,
                 const float* __restrict__ ln_g, const float* __restrict__ ln_b,
                 const float* __restrict__ Who, const float* __restrict__ bho,
                 float* __restrict__ out, int write_ctx)
{
    __shared__ float As[8][128];      // z tile   [k][m]
    __shared__ float Bs[8][132];      // W2 tile  [k][n] (padded)
    __shared__ float Cs[128][8];      // ctx slice for this CTA's K range
    __shared__ float s_h1[H_];
    __shared__ float s_hn[H_];
    __shared__ float s_red[32];

    const int tid = threadIdx.x;

    for (int t = 0; t < T_; t++) {
        const float* xt   = input + (size_t)t * (B_ * I_);
        const float* ctxp = g_ctx[t & 1];
        float*       ctxn = g_ctx[(t + 1) & 1];

        // ================= S1: heavy GEMM partials ==========================
        {
            const int nt = blockIdx.x & 3;
            const int ks = blockIdx.x >> 2;
            const int n0 = nt * 128;
            const int k0 = ks * KPER;
            const int c0 = k0 >> 6;              // 8 ctx columns per CTA

            const int m    = tid & 127;
            const int half = tid >> 7;           // 0/1
            // stage ctx slice [128m x 8c] into smem
            {
                float4 v = *(const float4*)&ctxp[m * C_ + c0 + half * 4];
                Cs[m][half * 4 + 0] = v.x; Cs[m][half * 4 + 1] = v.y;
                Cs[m][half * 4 + 2] = v.z; Cs[m][half * 4 + 3] = v.w;
            }
            float acc[8][8];
#pragma unroll
            for (int a = 0; a < 8; a++)
#pragma unroll
                for (int b = 0; b < 8; b++) acc[a][b] = 0.f;

            const int ty = tid >> 4, tx = tid & 15;
            const int nb = tid >> 1, kq = (tid & 1) * 4;
            __syncthreads();

            for (int kb = 0; kb < KPER; kb += 8) {
                const int kg = k0 + kb;
                const int cc = (kg >> 6) - c0;   // 0..7
                const int i0 = kg & 63;
                // A tile: z[m][kk] = ctx[m][c] * x[m][i0+kk]
                {
                    float cv = Cs[m][cc];
                    float4 xv = *(const float4*)&xt[m * I_ + i0 + half * 4];
                    As[half * 4 + 0][m] = cv * xv.x;
                    As[half * 4 + 1][m] = cv * xv.y;
                    As[half * 4 + 2][m] = cv * xv.z;
                    As[half * 4 + 3][m] = cv * xv.w;
                }
                // B tile: W2[n0+nb][kg + kq .. +3]
                {
                    float4 wv = *(const float4*)&g_W2[(size_t)(n0 + nb) * CI_ + kg + kq];
                    Bs[kq + 0][nb] = wv.x; Bs[kq + 1][nb] = wv.y;
                    Bs[kq + 2][nb] = wv.z; Bs[kq + 3][nb] = wv.w;
                }
                __syncthreads();
#pragma unroll
                for (int kk = 0; kk < 8; kk++) {
                    float a[8], b[8];
                    float4 a0 = *(const float4*)&As[kk][ty * 8];
                    float4 a1 = *(const float4*)&As[kk][ty * 8 + 4];
                    a[0]=a0.x; a[1]=a0.y; a[2]=a0.z; a[3]=a0.w;
                    a[4]=a1.x; a[5]=a1.y; a[6]=a1.z; a[7]=a1.w;
                    float4 b0 = *(const float4*)&Bs[kk][tx * 8];
                    float4 b1 = *(const float4*)&Bs[kk][tx * 8 + 4];
                    b[0]=b0.x; b[1]=b0.y; b[2]=b0.z; b[3]=b0.w;
                    b[4]=b1.x; b[5]=b1.y; b[6]=b1.z; b[7]=b1.w;
#pragma unroll
                    for (int im = 0; im < 8; im++)
#pragma unroll
                        for (int in = 0; in < 8; in++)
                            acc[im][in] += a[im] * b[in];
                }
                __syncthreads();
            }
            // store partial tile
            float* hp = g_hpart[ks];
#pragma unroll
            for (int im = 0; im < 8; im++) {
                int mm = ty * 8 + im;
                float4 v0 = make_float4(acc[im][0], acc[im][1], acc[im][2], acc[im][3]);
                float4 v1 = make_float4(acc[im][4], acc[im][5], acc[im][6], acc[im][7]);
                *(float4*)&hp[(size_t)mm * H_ + n0 + tx * 8]     = v0;
                *(float4*)&hp[(size_t)mm * H_ + n0 + tx * 8 + 4] = v1;
            }
        }
        grid_sync();

        // ================= S2: reduce + relu -> h1 ; ctx update ============
        {
            const int idx = blockIdx.x * NTHR + tid;   // 0..32767
            // h1: two elements per thread
#pragma unroll
            for (int p = 0; p < 2; p++) {
                const int e = idx + p * 32768;
                const int b = e >> 9, h = e & 511;
                float s = 0.f;
#pragma unroll
                for (int ks = 0; ks < KSPLIT; ks++) s += g_hpart[ks][e];
                const float* xr = xt + b * I_;
                const float* br = bmap + (size_t)h * I_;
#pragma unroll
                for (int i = 0; i < I_; i += 4) {
                    float4 xv = *(const float4*)&xr[i];
                    float4 bv = *(const float4*)&br[i];
                    s += xv.x * bv.x + xv.y * bv.y + xv.z * bv.z + xv.w * bv.w;
                }
                g_h1[e] = fmaxf(s, 0.f);
            }
            // ctx update (exact fp32; one element per thread)
            {
                const int b = idx >> 8, cc = idx & 255;
                float s = bcc[cc] + bic[cc];
                const float* cr = ctxp + b * C_;
                const float* wr = Wcc + (size_t)cc * C_;
#pragma unroll 8
                for (int c2 = 0; c2 < C_; c2 += 4) {
                    float4 cv = *(const float4*)&cr[c2];
                    float4 wv = *(const float4*)&wr[c2];
                    s += cv.x * wv.x + cv.y * wv.y + cv.z * wv.z + cv.w * wv.w;
                }
                const float* xr = xt + b * I_;
                const float* wi = Wic + (size_t)cc * I_;
#pragma unroll
                for (int i = 0; i < I_; i += 4) {
                    float4 xv = *(const float4*)&xr[i];
                    float4 wv = *(const float4*)&wi[i];
                    s += xv.x * wv.x + xv.y * wv.y + xv.z * wv.z + xv.w * wv.w;
                }
                ctxn[idx] = fmaxf(s, 0.f);
            }
        }
        grid_sync();

        // ================= S3: Whh + LayerNorm + residual + Who ============
        if (blockIdx.x < 32) {
            const int j2 = tid >> 1, hf = tid & 1;
            for (int r = 0; r < 4; r++) {
                const int b = blockIdx.x * 4 + r;
                s_h1[tid]       = g_h1[(size_t)b * H_ + tid];
                s_h1[tid + 256] = g_h1[(size_t)b * H_ + tid + 256];
                __syncthreads();
                // hn = h1 @ Whh^T + bhh   (2 threads per row)
#pragma unroll 1
                for (int p = 0; p < 4; p++) {
                    const int j = p * 128 + j2;
                    const float* w  = Whh + (size_t)j * H_ + hf * 256;
                    const float* hv = s_h1 + hf * 256;
                    float s = 0.f;
#pragma unroll 16
                    for (int h = 0; h < 256; h += 4) {
                        float4 wv = *(const float4*)&w[h];
                        s += hv[h] * wv.x + hv[h+1] * wv.y + hv[h+2] * wv.z + hv[h+3] * wv.w;
                    }
                    s += __shfl_xor_sync(0xffffffffu, s, 1);
                    if (hf == 0) s_hn[j] = s + bhh[j];
                }
                __syncthreads();
                // layernorm stats
                float v0 = s_hn[tid], v1 = s_hn[tid + 256];
                float ss = v0 + v1, sq = v0 * v0 + v1 * v1;
#pragma unroll
                for (int o = 16; o; o >>= 1) {
                    ss += __shfl_xor_sync(0xffffffffu, ss, o);
                    sq += __shfl_xor_sync(0xffffffffu, sq, o);
                }
                if ((tid & 31) == 0) { s_red[tid >> 5] = ss; s_red[8 + (tid >> 5)] = sq; }
                __syncthreads();
                if (tid == 0) {
                    float S = 0.f, Q = 0.f;
#pragma unroll
                    for (int w = 0; w < 8; w++) { S += s_red[w]; Q += s_red[8 + w]; }
                    float mu  = S / (float)H_;
                    float var = Q / (float)H_ - mu * mu;
                    s_red[16] = mu;
                    s_red[17] = rsqrtf(var + 1e-5f);
                }
                __syncthreads();
                const float mu = s_red[16], rs = s_red[17];
#pragma unroll
                for (int jj = 0; jj < 2; jj++) {
                    const int j = tid + jj * 256;
                    float ln = (s_hn[j] - mu) * rs * ln_g[j] + ln_b[j];
                    s_hn[j] = s_h1[j] + fmaxf(ln, 0.f);
                }
                __syncthreads();
                // out = h2 @ Who^T + bho  (2 threads per output)
                {
                    const int o = tid >> 1;
                    const float* w  = Who + (size_t)o * H_ + hf * 256;
                    const float* hv = s_hn + hf * 256;
                    float s = 0.f;
#pragma unroll 16
                    for (int h = 0; h < 256; h += 4) {
                        float4 wv = *(const float4*)&w[h];
                        s += hv[h] * wv.x + hv[h+1] * wv.y + hv[h+2] * wv.z + hv[h+3] * wv.w;
                    }
                    s += __shfl_xor_sync(0xffffffffu, s, 1);
                    if (hf == 0) out[(size_t)t * (B_ * O_) + b * O_ + o] = s + bho[o];
                }
                __syncthreads();
            }
        } else if (blockIdx.x < 64) {
            // final ctx write-out (second output of the reference tuple)
            if (t == T_ - 1 && write_ctx) {
                const int idx = (blockIdx.x - 32) * NTHR + tid;   // 0..8191
                float4 v = *(const float4*)&g_ctx[0][idx * 4];    // (T)&1 == 0
                *(float4*)&out[(size_t)T_ * (B_ * O_) + (size_t)idx * 4] = v;
            }
        }
        grid_sync();
    }
}

// -------------------- launch ------------------------------------------------
extern "C" void kernel_launch(void* const* d_in, const int* in_sizes, int n_in,
                              void* d_out, int out_size) {
    const float* input = (const float*)d_in[0];
    const float* Wcc   = (const float*)d_in[1];
    const float* bcc   = (const float*)d_in[2];
    const float* Wic   = (const float*)d_in[3];
    const float* bic   = (const float*)d_in[4];
    const float* Wmap  = (const float*)d_in[5];
    const float* bmap  = (const float*)d_in[6];
    const float* Whh   = (const float*)d_in[7];
    const float* bhh   = (const float*)d_in[8];
    const float* ln_g  = (const float*)d_in[9];
    const float* ln_b  = (const float*)d_in[10];
    const float* Who   = (const float*)d_in[11];
    const float* bho   = (const float*)d_in[12];
    float* out = (float*)d_out;

    setup_kernel<<<8192, 256>>>(Wmap);

    int write_ctx = (out_size >= T_ * B_ * O_ + B_ * C_) ? 1 : 0;
    ctrnn_persistent<<<NCTA, NTHR>>>(input, Wcc, bcc, Wic, bic, bmap,
                                     Whh, bhh, ln_g, ln_b, Who, bho,
                                     out, write_ctx);
}

// round 13
// speedup vs baseline: 1.0024x; 1.0014x over previous
#include <cuda_runtime.h>
#include <cstdint>
#include <cstddef>

#define T_ 256
#define B_ 128
#define I_ 64
#define C_ 256
#define H_ 512
#define O_ 128
#define CI_ 16384      // C_*I_
#define NCTA 128
#define NTHR 256
#define KSPLIT 32
#define KPER 512       // CI_/KSPLIT

// -------------------- scratch (static device allocations are allowed) ------
__device__ float g_W2[(size_t)H_ * CI_];            // 32 MB: W2[h][c*I+i] = Wmap[(h*I+i)*C + c]
__device__ float g_ctx[2][B_ * C_];                 // ctx double buffer
__device__ float g_hpart[KSPLIT][B_ * H_];          // 8 MB partial sums of heavy GEMM
__device__ float g_h1[B_ * H_];                     // h after relu
__device__ unsigned g_cnt;
__device__ volatile unsigned g_gen;

// -------------------- grid-wide barrier (all NCTA CTAs co-resident) --------
__device__ __forceinline__ void grid_sync() {
    __syncthreads();
    if (threadIdx.x == 0) {
        __threadfence();
        unsigned gen = g_gen;
        if (atomicAdd(&g_cnt, 1u) == NCTA - 1) {
            g_cnt = 0;
            __threadfence();
            g_gen = gen + 1;
        } else {
            while (g_gen == gen) { __nanosleep(64); }
        }
        __threadfence();
    }
    __syncthreads();
}

// -------------------- setup: build W2, zero ctx0 ----------------------------
__global__ void setup_kernel(const float* __restrict__ Wmap) {
    size_t e4 = (size_t)blockIdx.x * blockDim.x + threadIdx.x;
    size_t base = e4 * 4;
    if (base < (size_t)H_ * CI_) {
#pragma unroll
        for (int j = 0; j < 4; j++) {
            size_t e = base + j;
            int h = (int)(e >> 14);          // e / CI_
            int k = (int)(e & (CI_ - 1));
            int c = k >> 6, i = k & 63;
            g_W2[e] = Wmap[((size_t)h * I_ + i) * C_ + c];
        }
    }
    if (blockIdx.x < 32) {
        int z = blockIdx.x * blockDim.x + threadIdx.x;
#pragma unroll
        for (int j = 0; j < 4; j++) g_ctx[0][z * 4 + j] = 0.f;
    }
}

// -------------------- persistent timestep kernel ----------------------------
__global__ void __launch_bounds__(NTHR)
ctrnn_persistent(const float* __restrict__ input,
                 const float* __restrict__ Wcc, const float* __restrict__ bcc,
                 const float* __restrict__ Wic, const float* __restrict__ bic,
                 const float* __restrict__ bmap,
                 const float* __restrict__ Whh, const float* __restrict__ bhh,
                 const float* __restrict__ ln_g, const float* __restrict__ ln_b,
                 const float* __restrict__ Who, const float* __restrict__ bho,
                 float* __restrict__ out, int write_ctx)
{
    __shared__ float As[8][128];      // z tile   [k][m]
    __shared__ float Bs[8][132];      // W2 tile  [k][n] (padded)
    __shared__ float Cs[128][8];      // ctx slice for this CTA's K range
    __shared__ float s_h1[H_];
    __shared__ float s_hn[H_];
    __shared__ float s_red[32];

    const int tid = threadIdx.x;

    for (int t = 0; t < T_; t++) {
        const float* xt   = input + (size_t)t * (B_ * I_);
        const float* ctxp = g_ctx[t & 1];
        float*       ctxn = g_ctx[(t + 1) & 1];

        // ================= S1: heavy GEMM partials ==========================
        {
            const int nt = blockIdx.x & 3;
            const int ks = blockIdx.x >> 2;
            const int n0 = nt * 128;
            const int k0 = ks * KPER;
            const int c0 = k0 >> 6;              // 8 ctx columns per CTA

            const int m    = tid & 127;
            const int half = tid >> 7;           // 0/1
            // stage ctx slice [128m x 8c] into smem
            {
                float4 v = *(const float4*)&ctxp[m * C_ + c0 + half * 4];
                Cs[m][half * 4 + 0] = v.x; Cs[m][half * 4 + 1] = v.y;
                Cs[m][half * 4 + 2] = v.z; Cs[m][half * 4 + 3] = v.w;
            }
            float acc[8][8];
#pragma unroll
            for (int a = 0; a < 8; a++)
#pragma unroll
                for (int b = 0; b < 8; b++) acc[a][b] = 0.f;

            const int ty = tid >> 4, tx = tid & 15;
            const int nb = tid >> 1, kq = (tid & 1) * 4;
            __syncthreads();

            for (int kb = 0; kb < KPER; kb += 8) {
                const int kg = k0 + kb;
                const int cc = (kg >> 6) - c0;   // 0..7
                const int i0 = kg & 63;
                // A tile: z[m][kk] = ctx[m][c] * x[m][i0+kk]
                {
                    float cv = Cs[m][cc];
                    float4 xv = *(const float4*)&xt[m * I_ + i0 + half * 4];
                    As[half * 4 + 0][m] = cv * xv.x;
                    As[half * 4 + 1][m] = cv * xv.y;
                    As[half * 4 + 2][m] = cv * xv.z;
                    As[half * 4 + 3][m] = cv * xv.w;
                }
                // B tile: W2[n0+nb][kg + kq .. +3]
                {
                    float4 wv = *(const float4*)&g_W2[(size_t)(n0 + nb) * CI_ + kg + kq];
                    Bs[kq + 0][nb] = wv.x; Bs[kq + 1][nb] = wv.y;
                    Bs[kq + 2][nb] = wv.z; Bs[kq + 3][nb] = wv.w;
                }
                __syncthreads();
#pragma unroll
                for (int kk = 0; kk < 8; kk++) {
                    float a[8], b[8];
                    float4 a0 = *(const float4*)&As[kk][ty * 8];
                    float4 a1 = *(const float4*)&As[kk][ty * 8 + 4];
                    a[0]=a0.x; a[1]=a0.y; a[2]=a0.z; a[3]=a0.w;
                    a[4]=a1.x; a[5]=a1.y; a[6]=a1.z; a[7]=a1.w;
                    float4 b0 = *(const float4*)&Bs[kk][tx * 8];
                    float4 b1 = *(const float4*)&Bs[kk][tx * 8 + 4];
                    b[0]=b0.x; b[1]=b0.y; b[2]=b0.z; b[3]=b0.w;
                    b[4]=b1.x; b[5]=b1.y; b[6]=b1.z; b[7]=b1.w;
#pragma unroll
                    for (int im = 0; im < 8; im++)
#pragma unroll
                        for (int in = 0; in < 8; in++)
                            acc[im][in] += a[im] * b[in];
                }
                __syncthreads();
            }
            // store partial tile
            float* hp = g_hpart[ks];
#pragma unroll
            for (int im = 0; im < 8; im++) {
                int mm = ty * 8 + im;
                float4 v0 = make_float4(acc[im][0], acc[im][1], acc[im][2], acc[im][3]);
                float4 v1 = make_float4(acc[im][4], acc[im][5], acc[im][6], acc[im][7]);
                *(float4*)&hp[(size_t)mm * H_ + n0 + tx * 8]     = v0;
                *(float4*)&hp[(size_t)mm * H_ + n0 + tx * 8 + 4] = v1;
            }
        }
        grid_sync();

        // ================= S2: reduce + relu -> h1 ; ctx update ============
        {
            const int idx = blockIdx.x * NTHR + tid;   // 0..32767
            // h1: two elements per thread
#pragma unroll
            for (int p = 0; p < 2; p++) {
                const int e = idx + p * 32768;
                const int b = e >> 9, h = e & 511;
                float s = 0.f;
#pragma unroll
                for (int ks = 0; ks < KSPLIT; ks++) s += g_hpart[ks][e];
                const float* xr = xt + b * I_;
                const float* br = bmap + (size_t)h * I_;
#pragma unroll
                for (int i = 0; i < I_; i += 4) {
                    float4 xv = *(const float4*)&xr[i];
                    float4 bv = *(const float4*)&br[i];
                    s += xv.x * bv.x + xv.y * bv.y + xv.z * bv.z + xv.w * bv.w;
                }
                g_h1[e] = fmaxf(s, 0.f);
            }
            // ctx update (exact fp32; one element per thread)
            {
                const int b = idx >> 8, cc = idx & 255;
                float s = bcc[cc] + bic[cc];
                const float* cr = ctxp + b * C_;
                const float* wr = Wcc + (size_t)cc * C_;
#pragma unroll 8
                for (int c2 = 0; c2 < C_; c2 += 4) {
                    float4 cv = *(const float4*)&cr[c2];
                    float4 wv = *(const float4*)&wr[c2];
                    s += cv.x * wv.x + cv.y * wv.y + cv.z * wv.z + cv.w * wv.w;
                }
                const float* xr = xt + b * I_;
                const float* wi = Wic + (size_t)cc * I_;
#pragma unroll
                for (int i = 0; i < I_; i += 4) {
                    float4 xv = *(const float4*)&xr[i];
                    float4 wv = *(const float4*)&wi[i];
                    s += xv.x * wv.x + xv.y * wv.y + xv.z * wv.z + xv.w * wv.w;
                }
                ctxn[idx] = fmaxf(s, 0.f);
            }
        }
        grid_sync();

        // ================= S3: Whh + LayerNorm + residual + Who ============
        if (blockIdx.x < 32) {
            const int j2 = tid >> 1, hf = tid & 1;
            for (int r = 0; r < 4; r++) {
                const int b = blockIdx.x * 4 + r;
                s_h1[tid]       = g_h1[(size_t)b * H_ + tid];
                s_h1[tid + 256] = g_h1[(size_t)b * H_ + tid + 256];
                __syncthreads();
                // hn = h1 @ Whh^T + bhh   (2 threads per row)
#pragma unroll 1
                for (int p = 0; p < 4; p++) {
                    const int j = p * 128 + j2;
                    const float* w  = Whh + (size_t)j * H_ + hf * 256;
                    const float* hv = s_h1 + hf * 256;
                    float s = 0.f;
#pragma unroll 16
                    for (int h = 0; h < 256; h += 4) {
                        float4 wv = *(const float4*)&w[h];
                        s += hv[h] * wv.x + hv[h+1] * wv.y + hv[h+2] * wv.z + hv[h+3] * wv.w;
                    }
                    s += __shfl_xor_sync(0xffffffffu, s, 1);
                    if (hf == 0) s_hn[j] = s + bhh[j];
                }
                __syncthreads();
                // layernorm stats
                float v0 = s_hn[tid], v1 = s_hn[tid + 256];
                float ss = v0 + v1, sq = v0 * v0 + v1 * v1;
#pragma unroll
                for (int o = 16; o; o >>= 1) {
                    ss += __shfl_xor_sync(0xffffffffu, ss, o);
                    sq += __shfl_xor_sync(0xffffffffu, sq, o);
                }
                if ((tid & 31) == 0) { s_red[tid >> 5] = ss; s_red[8 + (tid >> 5)] = sq; }
                __syncthreads();
                if (tid == 0) {
                    float S = 0.f, Q = 0.f;
#pragma unroll
                    for (int w = 0; w < 8; w++) { S += s_red[w]; Q += s_red[8 + w]; }
                    float mu  = S / (float)H_;
                    float var = Q / (float)H_ - mu * mu;
                    s_red[16] = mu;
                    s_red[17] = rsqrtf(var + 1e-5f);
                }
                __syncthreads();
                const float mu = s_red[16], rs = s_red[17];
#pragma unroll
                for (int jj = 0; jj < 2; jj++) {
                    const int j = tid + jj * 256;
                    float ln = (s_hn[j] - mu) * rs * ln_g[j] + ln_b[j];
                    s_hn[j] = s_h1[j] + fmaxf(ln, 0.f);
                }
                __syncthreads();
                // out = h2 @ Who^T + bho  (2 threads per output)
                {
                    const int o = tid >> 1;
                    const float* w  = Who + (size_t)o * H_ + hf * 256;
                    const float* hv = s_hn + hf * 256;
                    float s = 0.f;
#pragma unroll 16
                    for (int h = 0; h < 256; h += 4) {
                        float4 wv = *(const float4*)&w[h];
                        s += hv[h] * wv.x + hv[h+1] * wv.y + hv[h+2] * wv.z + hv[h+3] * wv.w;
                    }
                    s += __shfl_xor_sync(0xffffffffu, s, 1);
                    if (hf == 0) out[(size_t)t * (B_ * O_) + b * O_ + o] = s + bho[o];
                }
                __syncthreads();
            }
        } else if (blockIdx.x < 64) {
            // final ctx write-out (second output of the reference tuple)
            if (t == T_ - 1 && write_ctx) {
                const int idx = (blockIdx.x - 32) * NTHR + tid;   // 0..8191
                float4 v = *(const float4*)&g_ctx[0][idx * 4];    // (T)&1 == 0
                *(float4*)&out[(size_t)T_ * (B_ * O_) + (size_t)idx * 4] = v;
            }
        }
        grid_sync();
    }
}

// -------------------- launch ------------------------------------------------
extern "C" void kernel_launch(void* const* d_in, const int* in_sizes, int n_in,
                              void* d_out, int out_size) {
    const float* input = (const float*)d_in[0];
    const float* Wcc   = (const float*)d_in[1];
    const float* bcc   = (const float*)d_in[2];
    const float* Wic   = (const float*)d_in[3];
    const float* bic   = (const float*)d_in[4];
    const float* Wmap  = (const float*)d_in[5];
    const float* bmap  = (const float*)d_in[6];
    const float* Whh   = (const float*)d_in[7];
    const float* bhh   = (const float*)d_in[8];
    const float* ln_g  = (const float*)d_in[9];
    const float* ln_b  = (const float*)d_in[10];
    const float* Who   = (const float*)d_in[11];
    const float* bho   = (const float*)d_in[12];
    float* out = (float*)d_out;

    setup_kernel<<<8192, 256>>>(Wmap);

    int write_ctx = (out_size >= T_ * B_ * O_ + B_ * C_) ? 1 : 0;
    ctrnn_persistent<<<NCTA, NTHR>>>(input, Wcc, bcc, Wic, bic, bmap,
                                     Whh, bhh, ln_g, ln_b, Who, bho,
                                     out, write_ctx);
}